// round 1
// baseline (speedup 1.0000x reference)
#include <cuda_runtime.h>
#include <stdint.h>

// Problem constants
#define BB 8192
#define HH 1024
#define LL 1024
#define NHEAD 5

// GEMM tile config
#define TM 128
#define TN 64
#define TK 16
#define PADA 4
#define PADB 4
#define NTHREADS 256

// Scratch (no cudaMalloc allowed): bucket counters + gathered row lists
__device__ int g_cnt[8];
__device__ int g_rows[6 * BB];

__global__ void init_kernel() {
    if (threadIdx.x < 8) g_cnt[threadIdx.x] = 0;
}

__global__ void bucket_kernel(const int* __restrict__ group) {
    int b = blockIdx.x * blockDim.x + threadIdx.x;
    if (b < BB) {
        int g = group[b];
        if (g < 0) g = 0;
        if (g > 5) g = 5;
        int pos = atomicAdd(&g_cnt[g], 1);
        g_rows[g * BB + pos] = b;
    }
}

// Gather-GEMM: out[row, col] = sum_h hs[row, h] * W[head, col, h] + bias[head, col]
// for rows in bucket `head` (head = blockIdx.z, 0..4).
__global__ __launch_bounds__(NTHREADS)
void gemm_kernel(const float* __restrict__ hs,
                 const float* __restrict__ W,
                 const float* __restrict__ bias,
                 float* __restrict__ out) {
    const int head = blockIdx.z;
    const int count = g_cnt[head];
    const int row0 = blockIdx.y * TM;
    if (row0 >= count) return;
    const int col0 = blockIdx.x * TN;

    __shared__ float As[TK][TM + PADA];
    __shared__ float Bs[TK][TN + PADB];
    __shared__ int rowIdx[TM];

    const int tid = threadIdx.x;

    if (tid < TM) {
        int r = row0 + tid;
        rowIdx[tid] = (r < count) ? g_rows[head * BB + r] : -1;
    }
    __syncthreads();

    float acc[8][4];
#pragma unroll
    for (int i = 0; i < 8; i++)
#pragma unroll
        for (int j = 0; j < 4; j++) acc[i][j] = 0.0f;

    const int tx = tid & 15;   // 16 cols of threads -> 4 output cols each
    const int ty = tid >> 4;   // 16 rows of threads -> 8 output rows each

    const float* __restrict__ Wh = W + (size_t)head * LL * HH;

    for (int k0 = 0; k0 < HH; k0 += TK) {
        // Load A tile: TM x TK (gathered rows), 2x float4 per thread
#pragma unroll
        for (int li = 0; li < 2; li++) {
            int idx = tid + li * NTHREADS;   // 0..511
            int r = idx >> 2;                // 0..127
            int kq = idx & 3;                // which float4 of TK
            int row = rowIdx[r];
            float4 v = make_float4(0.f, 0.f, 0.f, 0.f);
            if (row >= 0)
                v = *reinterpret_cast<const float4*>(&hs[(size_t)row * HH + k0 + kq * 4]);
            As[kq * 4 + 0][r] = v.x;
            As[kq * 4 + 1][r] = v.y;
            As[kq * 4 + 2][r] = v.z;
            As[kq * 4 + 3][r] = v.w;
        }
        // Load B tile: TN x TK, 1x float4 per thread
        {
            int c  = tid >> 2;   // 0..63
            int kq = tid & 3;
            float4 v = *reinterpret_cast<const float4*>(
                &Wh[(size_t)(col0 + c) * HH + k0 + kq * 4]);
            Bs[kq * 4 + 0][c] = v.x;
            Bs[kq * 4 + 1][c] = v.y;
            Bs[kq * 4 + 2][c] = v.z;
            Bs[kq * 4 + 3][c] = v.w;
        }
        __syncthreads();

#pragma unroll
        for (int kk = 0; kk < TK; kk++) {
            float4 a0 = *reinterpret_cast<const float4*>(&As[kk][ty * 8]);
            float4 a1 = *reinterpret_cast<const float4*>(&As[kk][ty * 8 + 4]);
            float4 b0 = *reinterpret_cast<const float4*>(&Bs[kk][tx * 4]);
            float a[8] = {a0.x, a0.y, a0.z, a0.w, a1.x, a1.y, a1.z, a1.w};
            float bb[4] = {b0.x, b0.y, b0.z, b0.w};
#pragma unroll
            for (int i = 0; i < 8; i++)
#pragma unroll
                for (int j = 0; j < 4; j++)
                    acc[i][j] = fmaf(a[i], bb[j], acc[i][j]);
        }
        __syncthreads();
    }

    // Epilogue: bias + scattered store
#pragma unroll
    for (int i = 0; i < 8; i++) {
        int r = ty * 8 + i;
        int row = rowIdx[r];
        if (row >= 0) {
            float4 v;
            int c = col0 + tx * 4;
            v.x = acc[i][0] + bias[head * LL + c + 0];
            v.y = acc[i][1] + bias[head * LL + c + 1];
            v.z = acc[i][2] + bias[head * LL + c + 2];
            v.w = acc[i][3] + bias[head * LL + c + 3];
            *reinterpret_cast<float4*>(&out[(size_t)row * LL + c]) = v;
        }
    }
}

// group==5 rows: fill entire row with (float)labels[row]
__global__ void fill_kernel(const int* __restrict__ labels, float* __restrict__ out) {
    int i = blockIdx.x;
    if (i >= g_cnt[5]) return;
    int row = g_rows[5 * BB + i];
    float v = (float)labels[row];
    float4 v4 = make_float4(v, v, v, v);
    int c = threadIdx.x * 4;
    *reinterpret_cast<float4*>(&out[(size_t)row * LL + c]) = v4;
}

extern "C" void kernel_launch(void* const* d_in, const int* in_sizes, int n_in,
                              void* d_out, int out_size) {
    const float* hs     = (const float*)d_in[0];  // [B, H]
    const float* W      = (const float*)d_in[1];  // [5, L, H]
    const float* bias   = (const float*)d_in[2];  // [5, L]
    const int*   group  = (const int*)d_in[3];    // [B]
    const int*   labels = (const int*)d_in[4];    // [B]
    float* out = (float*)d_out;                   // [B, L]

    init_kernel<<<1, 32>>>();
    bucket_kernel<<<BB / 256, 256>>>(group);

    dim3 grid(LL / TN, (BB + TM - 1) / TM, NHEAD);
    gemm_kernel<<<grid, NTHREADS>>>(hs, W, bias, out);

    fill_kernel<<<BB, LL / 4>>>(labels, out);
}

// round 3
// speedup vs baseline: 2.9171x; 2.9171x over previous
#include <cuda_runtime.h>
#include <cuda_fp16.h>
#include <stdint.h>

// ---------------- problem constants ----------------
#define BB 8192
#define HH 1024
#define LL 1024
#define NHEAD 5

// ---------------- GEMM config ----------------
#define TM 128
#define TN 128
#define KC 32            // K elements per chunk
#define NC (HH / KC)     // 32 chunks
#define NSTAGE 3
#define NTHREADS 256

// smem: rowIdx (512B) then 3 stages of (Ahi 8K | Alo 8K | B 8K)
#define STAGE_BYTES (3 * 128 * 64)
#define SM_STAGE0 1024
#define SMEM_TOTAL (SM_STAGE0 + NSTAGE * STAGE_BYTES)

// ---------------- scratch ----------------
__device__ int g_cnt[8];
__device__ int g_pos[BB];
__device__ int g_rows[6 * BB];
__device__ __half g_ahi[(size_t)5 * BB * HH];
__device__ __half g_alo[(size_t)5 * BB * HH];
__device__ __half g_whi[(size_t)NHEAD * LL * HH];

// ---------------- PTX helpers ----------------
__device__ __forceinline__ uint32_t smem_u32(const void* p) {
    uint32_t a;
    asm("{ .reg .u64 t; cvta.to.shared.u64 t, %1; cvt.u32.u64 %0, t; }" : "=r"(a) : "l"(p));
    return a;
}
#define CP_ASYNC16(dst, src) \
    asm volatile("cp.async.cg.shared.global [%0], [%1], 16;" :: "r"(dst), "l"(src))
#define CP_COMMIT() asm volatile("cp.async.commit_group;" ::: "memory")
#define CP_WAIT1()  asm volatile("cp.async.wait_group 1;" ::: "memory")

__device__ __forceinline__ void ld_frag4(uint32_t* f, uint32_t sbase, int rowbase,
                                         int c16, int lane) {
    int r = rowbase + (lane & 15);
    int cc = c16 + (lane >> 4);
    uint32_t addr = sbase + r * 64 + (((cc ^ ((r >> 1) & 3))) << 4);
    asm volatile("ldmatrix.sync.aligned.m8n8.x4.shared.b16 {%0,%1,%2,%3}, [%4];"
                 : "=r"(f[0]), "=r"(f[1]), "=r"(f[2]), "=r"(f[3]) : "r"(addr));
}

__device__ __forceinline__ void mma16816(float* d, const uint32_t* a,
                                         uint32_t b0, uint32_t b1) {
    asm volatile(
        "mma.sync.aligned.m16n8k16.row.col.f32.f16.f16.f32 "
        "{%0,%1,%2,%3}, {%4,%5,%6,%7}, {%8,%9}, {%0,%1,%2,%3};"
        : "+f"(d[0]), "+f"(d[1]), "+f"(d[2]), "+f"(d[3])
        : "r"(a[0]), "r"(a[1]), "r"(a[2]), "r"(a[3]), "r"(b0), "r"(b1));
}

__device__ __forceinline__ uint32_t packh2(__half a, __half b) {
    __half2 t(a, b);
    return *reinterpret_cast<uint32_t*>(&t);
}

// ---------------- aux kernels ----------------
__global__ void init_kernel() {
    if (threadIdx.x < 8) g_cnt[threadIdx.x] = 0;
}

__global__ void bucket_kernel(const int* __restrict__ group) {
    int b = blockIdx.x * blockDim.x + threadIdx.x;
    if (b < BB) {
        int g = group[b];
        if (g < 0) g = 0;
        if (g > 5) g = 5;
        int pos = atomicAdd(&g_cnt[g], 1);
        g_pos[b] = pos;
        g_rows[g * BB + pos] = b;
    }
}

// W fp32 -> fp16 hi
__global__ void convert_w_kernel(const float* __restrict__ W) {
    int i = blockIdx.x * blockDim.x + threadIdx.x;   // float4 index
    float4 f = reinterpret_cast<const float4*>(W)[i];
    uint2 hv = make_uint2(packh2(__float2half(f.x), __float2half(f.y)),
                          packh2(__float2half(f.z), __float2half(f.w)));
    reinterpret_cast<uint2*>(g_whi)[i] = hv;
}

// gather hidden rows into head-contiguous fp16 hi/lo buffers
__global__ void gather_a_kernel(const float* __restrict__ hs,
                                const int* __restrict__ group) {
    int b = blockIdx.x;
    int g = group[b];
    if (g < 0) g = 0;
    if (g > 5) g = 5;
    if (g == 5) return;
    size_t dst = (size_t)(g * BB + g_pos[b]) * HH;
    int t = threadIdx.x;                     // 256 threads, HH/4 float4s
    float4 f = reinterpret_cast<const float4*>(hs + (size_t)b * HH)[t];
    __half h0 = __float2half(f.x), h1 = __float2half(f.y);
    __half h2 = __float2half(f.z), h3 = __float2half(f.w);
    __half l0 = __float2half(f.x - __half2float(h0));
    __half l1 = __float2half(f.y - __half2float(h1));
    __half l2 = __float2half(f.z - __half2float(h2));
    __half l3 = __float2half(f.w - __half2float(h3));
    reinterpret_cast<uint2*>(g_ahi + dst)[t] = make_uint2(packh2(h0, h1), packh2(h2, h3));
    reinterpret_cast<uint2*>(g_alo + dst)[t] = make_uint2(packh2(l0, l1), packh2(l2, l3));
}

__global__ void fill_kernel(const int* __restrict__ labels, float* __restrict__ out) {
    for (int i = blockIdx.x; i < g_cnt[5]; i += gridDim.x) {
        int row = g_rows[5 * BB + i];
        float v = (float)labels[row];
        float4 v4 = make_float4(v, v, v, v);
        reinterpret_cast<float4*>(out + (size_t)row * LL)[threadIdx.x] = v4;
    }
}

// ---------------- HMMA GEMM ----------------
// grid: (LL/TN=8, BB/TM=64, NHEAD). Early exit if row0 >= bucket count.
__global__ __launch_bounds__(NTHREADS, 2)
void gemm_hmma_kernel(const float* __restrict__ bias, float* __restrict__ out) {
    const int head = blockIdx.z;
    const int cnt = g_cnt[head];
    const int row0 = blockIdx.y * TM;
    if (row0 >= cnt) return;
    const int col0 = blockIdx.x * TN;

    extern __shared__ char smem[];
    const uint32_t sb = smem_u32(smem);
    int* rowIdx_s = reinterpret_cast<int*>(smem);

    const int tid = threadIdx.x;
    const int wid = tid >> 5;
    const int lid = tid & 31;
    const int WM = (wid & 1) * 64;       // warp m offset (2 x 64)
    const int WN = (wid >> 1) * 32;      // warp n offset (4 x 32)

    if (tid < TM) {
        int r = row0 + tid;
        rowIdx_s[tid] = (r < cnt) ? g_rows[head * BB + r] : -1;
    }

    const __half* __restrict__ ahi = g_ahi + (size_t)(head * BB + row0) * HH;
    const __half* __restrict__ alo = g_alo + (size_t)(head * BB + row0) * HH;
    const __half* __restrict__ bmat = g_whi + ((size_t)head * LL + col0) * HH;

    // stage fill: 6 x 16B cp.async per thread (Ahi, Alo, B: 128 rows x 64B each)
    auto fill_stage = [&](int s, int chunk) {
        const int k0 = chunk * KC;
        const uint32_t sbase = sb + SM_STAGE0 + s * STAGE_BYTES;
#pragma unroll
        for (int l = 0; l < 6; l++) {
            const int mat = l >> 1;                    // 0=Ahi 1=Alo 2=B
            const int q = ((l & 1) << 8) + tid;        // 0..511
            const int r = q >> 2;
            const int cch = q & 3;
            const __half* src =
                (mat == 0 ? ahi : (mat == 1 ? alo : bmat)) + (size_t)r * HH + k0 + cch * 8;
            uint32_t dst = sbase + mat * 8192 + r * 64 + ((cch ^ ((r >> 1) & 3)) << 4);
            CP_ASYNC16(dst, src);
        }
    };

    // prologue: chunks 0,1
    fill_stage(0, 0); CP_COMMIT();
    fill_stage(1, 1); CP_COMMIT();

    float acc[4][4][4];
#pragma unroll
    for (int i = 0; i < 4; i++)
#pragma unroll
        for (int j = 0; j < 4; j++)
#pragma unroll
            for (int k = 0; k < 4; k++) acc[i][j][k] = 0.0f;

    for (int c = 0; c < NC; c++) {
        CP_WAIT1();                 // chunk c resident
        __syncthreads();            // prev-iter readers done + cross-thread visibility

        const uint32_t sbase = sb + SM_STAGE0 + (c % NSTAGE) * STAGE_BYTES;
        const uint32_t sAhi = sbase;
        const uint32_t sAlo = sbase + 8192;
        const uint32_t sB   = sbase + 16384;

#pragma unroll
        for (int kt = 0; kt < 2; kt++) {
            const int c16 = kt * 2;
            uint32_t bfr[8];
            ld_frag4(bfr + 0, sB, WN,      c16, lid);   // n8 tiles 0,1
            ld_frag4(bfr + 4, sB, WN + 16, c16, lid);   // n8 tiles 2,3
            uint32_t afr[16];
#pragma unroll
            for (int mt = 0; mt < 4; mt++) ld_frag4(afr + mt * 4, sAhi, WM + mt * 16, c16, lid);
#pragma unroll
            for (int mt = 0; mt < 4; mt++) {
                mma16816(acc[mt][0], afr + mt * 4, bfr[0], bfr[2]);
                mma16816(acc[mt][1], afr + mt * 4, bfr[1], bfr[3]);
                mma16816(acc[mt][2], afr + mt * 4, bfr[4], bfr[6]);
                mma16816(acc[mt][3], afr + mt * 4, bfr[5], bfr[7]);
            }
#pragma unroll
            for (int mt = 0; mt < 4; mt++) ld_frag4(afr + mt * 4, sAlo, WM + mt * 16, c16, lid);
#pragma unroll
            for (int mt = 0; mt < 4; mt++) {
                mma16816(acc[mt][0], afr + mt * 4, bfr[0], bfr[2]);
                mma16816(acc[mt][1], afr + mt * 4, bfr[1], bfr[3]);
                mma16816(acc[mt][2], afr + mt * 4, bfr[4], bfr[6]);
                mma16816(acc[mt][3], afr + mt * 4, bfr[5], bfr[7]);
            }
        }

        __syncthreads();            // readers of this stage done before refill
        if (c + 2 < NC) fill_stage((c + 2) % NSTAGE, c + 2);
        CP_COMMIT();                // always commit to keep group arithmetic uniform
    }

    // ---------------- epilogue ----------------
    const int groupID = lid >> 2;
    const int tig = lid & 3;
    const float* brow = bias + head * LL;

#pragma unroll
    for (int mt = 0; mt < 4; mt++) {
        const int mlo = WM + mt * 16 + groupID;
        const int mhi = mlo + 8;
        const int r1 = rowIdx_s[mlo];
        const int r2 = rowIdx_s[mhi];
#pragma unroll
        for (int nt = 0; nt < 4; nt++) {
            const int gc = col0 + WN + nt * 8 + tig * 2;
            const float2 bs = *reinterpret_cast<const float2*>(brow + gc);
            if (r1 >= 0) {
                float2 v = make_float2(acc[mt][nt][0] + bs.x, acc[mt][nt][1] + bs.y);
                *reinterpret_cast<float2*>(out + (size_t)r1 * LL + gc) = v;
            }
            if (r2 >= 0) {
                float2 v = make_float2(acc[mt][nt][2] + bs.x, acc[mt][nt][3] + bs.y);
                *reinterpret_cast<float2*>(out + (size_t)r2 * LL + gc) = v;
            }
        }
    }
}

// ---------------- launch ----------------
extern "C" void kernel_launch(void* const* d_in, const int* in_sizes, int n_in,
                              void* d_out, int out_size) {
    const float* hs     = (const float*)d_in[0];  // [B, H]
    const float* W      = (const float*)d_in[1];  // [5, L, H]
    const float* bias   = (const float*)d_in[2];  // [5, L]
    const int*   group  = (const int*)d_in[3];    // [B]
    const int*   labels = (const int*)d_in[4];    // [B]
    float* out = (float*)d_out;                   // [B, L]

    cudaFuncSetAttribute(gemm_hmma_kernel,
                         cudaFuncAttributeMaxDynamicSharedMemorySize, SMEM_TOTAL);

    init_kernel<<<1, 32>>>();
    bucket_kernel<<<BB / 256, 256>>>(group);
    convert_w_kernel<<<(NHEAD * LL * HH / 4) / 256, 256>>>(W);
    gather_a_kernel<<<BB, 256>>>(hs, group);

    dim3 grid(LL / TN, BB / TM, NHEAD);
    gemm_hmma_kernel<<<grid, NTHREADS, SMEM_TOTAL>>>(bias, out);

    fill_kernel<<<2048, 256>>>(labels, out);
}

// round 6
// speedup vs baseline: 4.5282x; 1.5523x over previous
#include <cuda_runtime.h>
#include <cuda_fp16.h>
#include <stdint.h>

// ---------------- problem constants ----------------
#define BB 8192
#define HH 1024
#define LL 1024
#define NHEAD 5

// ---------------- GEMM config ----------------
#define TM 128
#define TN 128
#define KC 32            // K elements per chunk
#define NC (HH / KC)     // 32 chunks
#define NSTAGE 4
#define NTHREADS 128     // 4 warps, 64x64 warp tiles

// smem: rowIdx (512B pad to 1K) then 4 stages of (A 8K | B 8K)
#define STAGE_BYTES (2 * 128 * 64)
#define SM_STAGE0 1024
#define SMEM_TOTAL (SM_STAGE0 + NSTAGE * STAGE_BYTES)

// ---------------- scratch ----------------
__device__ int g_cnt[8];
__device__ int g_pos[BB];
__device__ int g_rows[6 * BB];
__device__ __half g_ahi[(size_t)5 * BB * HH];
__device__ __half g_whi[(size_t)NHEAD * LL * HH];

// ---------------- PTX helpers ----------------
__device__ __forceinline__ uint32_t smem_u32(const void* p) {
    uint32_t a;
    asm("{ .reg .u64 t; cvta.to.shared.u64 t, %1; cvt.u32.u64 %0, t; }" : "=r"(a) : "l"(p));
    return a;
}
#define CP_ASYNC16(dst, src) \
    asm volatile("cp.async.cg.shared.global [%0], [%1], 16;" :: "r"(dst), "l"(src))
#define CP_COMMIT() asm volatile("cp.async.commit_group;" ::: "memory")
#define CP_WAIT2()  asm volatile("cp.async.wait_group 2;" ::: "memory")

__device__ __forceinline__ void ld_frag4(uint32_t* f, uint32_t sbase, int rowbase,
                                         int c16, int lane) {
    int r = rowbase + (lane & 15);
    int cc = c16 + (lane >> 4);
    uint32_t addr = sbase + r * 64 + (((cc ^ ((r >> 1) & 3))) << 4);
    asm volatile("ldmatrix.sync.aligned.m8n8.x4.shared.b16 {%0,%1,%2,%3}, [%4];"
                 : "=r"(f[0]), "=r"(f[1]), "=r"(f[2]), "=r"(f[3]) : "r"(addr));
}

__device__ __forceinline__ void mma16816(float* d, const uint32_t* a,
                                         uint32_t b0, uint32_t b1) {
    asm volatile(
        "mma.sync.aligned.m16n8k16.row.col.f32.f16.f16.f32 "
        "{%0,%1,%2,%3}, {%4,%5,%6,%7}, {%8,%9}, {%0,%1,%2,%3};"
        : "+f"(d[0]), "+f"(d[1]), "+f"(d[2]), "+f"(d[3])
        : "r"(a[0]), "r"(a[1]), "r"(a[2]), "r"(a[3]), "r"(b0), "r"(b1));
}

__device__ __forceinline__ uint32_t packh2(__half a, __half b) {
    __half2 t(a, b);
    return *reinterpret_cast<uint32_t*>(&t);
}

// ---------------- aux kernels ----------------
__global__ void init_kernel() {
    if (threadIdx.x < 8) g_cnt[threadIdx.x] = 0;
}

__global__ void bucket_kernel(const int* __restrict__ group) {
    int b = blockIdx.x * blockDim.x + threadIdx.x;
    if (b < BB) {
        int g = group[b];
        if (g < 0) g = 0;
        if (g > 5) g = 5;
        int pos = atomicAdd(&g_cnt[g], 1);
        g_pos[b] = pos;
        g_rows[g * BB + pos] = b;
    }
}

// W fp32 -> fp16
__global__ void convert_w_kernel(const float* __restrict__ W) {
    int i = blockIdx.x * blockDim.x + threadIdx.x;   // float4 index
    float4 f = reinterpret_cast<const float4*>(W)[i];
    uint2 hv = make_uint2(packh2(__float2half(f.x), __float2half(f.y)),
                          packh2(__float2half(f.z), __float2half(f.w)));
    reinterpret_cast<uint2*>(g_whi)[i] = hv;
}

// gather hidden rows into head-contiguous fp16 buffer; 1 warp per row
__global__ void gather_a_kernel(const float* __restrict__ hs,
                                const int* __restrict__ group) {
    int b = (blockIdx.x * blockDim.x + threadIdx.x) >> 5;
    int lane = threadIdx.x & 31;
    if (b >= BB) return;
    int g = group[b];
    if (g < 0) g = 0;
    if (g > 5) g = 5;
    if (g == 5) return;
    size_t dst = (size_t)(g * BB + g_pos[b]) * HH;
    const float4* src = reinterpret_cast<const float4*>(hs + (size_t)b * HH);
    uint2* dp = reinterpret_cast<uint2*>(g_ahi + dst);
#pragma unroll
    for (int i = 0; i < 8; i++) {
        float4 f = src[lane + i * 32];
        dp[lane + i * 32] = make_uint2(packh2(__float2half(f.x), __float2half(f.y)),
                                       packh2(__float2half(f.z), __float2half(f.w)));
    }
}

__global__ void fill_kernel(const int* __restrict__ labels, float* __restrict__ out) {
    for (int i = blockIdx.x; i < g_cnt[5]; i += gridDim.x) {
        int row = g_rows[5 * BB + i];
        float v = (float)labels[row];
        float4 v4 = make_float4(v, v, v, v);
        reinterpret_cast<float4*>(out + (size_t)row * LL)[threadIdx.x] = v4;
    }
}

// ---------------- HMMA GEMM ----------------
// grid: (LL/TN=8, BB/TM=64, NHEAD). Early exit if row0 >= bucket count.
__global__ __launch_bounds__(NTHREADS)
void gemm_hmma_kernel(const float* __restrict__ bias, float* __restrict__ out) {
    const int head = blockIdx.z;
    const int cnt = g_cnt[head];
    const int row0 = blockIdx.y * TM;
    if (row0 >= cnt) return;
    const int col0 = blockIdx.x * TN;

    extern __shared__ char smem[];
    const uint32_t sb = smem_u32(smem);
    int* rowIdx_s = reinterpret_cast<int*>(smem);

    const int tid = threadIdx.x;
    const int wid = tid >> 5;
    const int lid = tid & 31;
    const int WM = (wid & 1) * 64;       // 2 warp-rows of 64
    const int WN = (wid >> 1) * 64;      // 2 warp-cols of 64

    if (tid < TM) {
        int r = row0 + tid;
        rowIdx_s[tid] = (r < cnt) ? g_rows[head * BB + r] : -1;
    }

    const __half* __restrict__ amat = g_ahi + (size_t)(head * BB + row0) * HH;
    const __half* __restrict__ bmat = g_whi + ((size_t)head * LL + col0) * HH;

    // stage fill: 8 x 16B cp.async per thread (A,B: 128 rows x 64B each)
    auto fill_stage = [&](int s, int chunk) {
        const int k0 = chunk * KC;
        const uint32_t sbase = sb + SM_STAGE0 + s * STAGE_BYTES;
#pragma unroll
        for (int l = 0; l < 8; l++) {
            const int idx = l * NTHREADS + tid;        // 0..1023
            const int mat = idx >> 9;                  // 0=A 1=B
            const int q = idx & 511;
            const int r = q >> 2;
            const int cch = q & 3;
            const __half* src = (mat ? bmat : amat) + (size_t)r * HH + k0 + cch * 8;
            uint32_t dst = sbase + mat * 8192 + r * 64 + ((cch ^ ((r >> 1) & 3)) << 4);
            CP_ASYNC16(dst, src);
        }
    };

    // prologue: chunks 0..2
    fill_stage(0, 0); CP_COMMIT();
    fill_stage(1, 1); CP_COMMIT();
    fill_stage(2, 2); CP_COMMIT();

    float acc[4][8][4];
#pragma unroll
    for (int i = 0; i < 4; i++)
#pragma unroll
        for (int j = 0; j < 8; j++)
#pragma unroll
            for (int k = 0; k < 4; k++) acc[i][j][k] = 0.0f;

    for (int c = 0; c < NC; c++) {
        CP_WAIT2();                 // chunks 0..c resident
        __syncthreads();            // + all readers of stage (c-1)%4 done

        const uint32_t sbase = sb + SM_STAGE0 + (c % NSTAGE) * STAGE_BYTES;
        const uint32_t sA = sbase;
        const uint32_t sB = sbase + 8192;

#pragma unroll
        for (int kt = 0; kt < 2; kt++) {
            const int c16 = kt * 2;
            uint32_t bfr[16];
#pragma unroll
            for (int nb = 0; nb < 4; nb++) ld_frag4(bfr + nb * 4, sB, WN + nb * 16, c16, lid);
            uint32_t afr[16];
#pragma unroll
            for (int mt = 0; mt < 4; mt++) ld_frag4(afr + mt * 4, sA, WM + mt * 16, c16, lid);
#pragma unroll
            for (int mt = 0; mt < 4; mt++)
#pragma unroll
                for (int nb = 0; nb < 4; nb++) {
                    mma16816(acc[mt][nb * 2 + 0], afr + mt * 4, bfr[nb * 4 + 0], bfr[nb * 4 + 2]);
                    mma16816(acc[mt][nb * 2 + 1], afr + mt * 4, bfr[nb * 4 + 1], bfr[nb * 4 + 3]);
                }
        }

        if (c + 3 < NC) fill_stage((c + 3) % NSTAGE, c + 3);
        CP_COMMIT();                // keep group count uniform
    }

    // ---------------- epilogue ----------------
    const int groupID = lid >> 2;
    const int tig = lid & 3;
    const float* brow = bias + head * LL;

#pragma unroll
    for (int mt = 0; mt < 4; mt++) {
        const int mlo = WM + mt * 16 + groupID;
        const int r1 = rowIdx_s[mlo];
        const int r2 = rowIdx_s[mlo + 8];
#pragma unroll
        for (int nt = 0; nt < 8; nt++) {
            const int gc = col0 + WN + nt * 8 + tig * 2;
            const float2 bs = *reinterpret_cast<const float2*>(brow + gc);
            if (r1 >= 0) {
                float2 v = make_float2(acc[mt][nt][0] + bs.x, acc[mt][nt][1] + bs.y);
                *reinterpret_cast<float2*>(out + (size_t)r1 * LL + gc) = v;
            }
            if (r2 >= 0) {
                float2 v = make_float2(acc[mt][nt][2] + bs.x, acc[mt][nt][3] + bs.y);
                *reinterpret_cast<float2*>(out + (size_t)r2 * LL + gc) = v;
            }
        }
    }
}

// ---------------- launch ----------------
extern "C" void kernel_launch(void* const* d_in, const int* in_sizes, int n_in,
                              void* d_out, int out_size) {
    const float* hs     = (const float*)d_in[0];  // [B, H]
    const float* W      = (const float*)d_in[1];  // [5, L, H]
    const float* bias   = (const float*)d_in[2];  // [5, L]
    const int*   group  = (const int*)d_in[3];    // [B]
    const int*   labels = (const int*)d_in[4];    // [B]
    float* out = (float*)d_out;                   // [B, L]

    cudaFuncSetAttribute(gemm_hmma_kernel,
                         cudaFuncAttributeMaxDynamicSharedMemorySize, SMEM_TOTAL);

    init_kernel<<<1, 32>>>();
    bucket_kernel<<<BB / 256, 256>>>(group);
    convert_w_kernel<<<(NHEAD * LL * HH / 4) / 256, 256>>>(W);
    gather_a_kernel<<<BB * 32 / 256, 256>>>(hs, group);

    dim3 grid(LL / TN, BB / TM, NHEAD);
    gemm_hmma_kernel<<<grid, NTHREADS, SMEM_TOTAL>>>(bias, out);

    fill_kernel<<<2048, 256>>>(labels, out);
}

// round 7
// speedup vs baseline: 5.3732x; 1.1866x over previous
#include <cuda_runtime.h>
#include <cuda_fp16.h>
#include <cuda_fp8.h>
#include <stdint.h>

// ---------------- problem constants ----------------
#define BB 8192
#define HH 1024
#define LL 1024
#define NHEAD 5

// ---------------- GEMM config ----------------
#define TM 128
#define TN 128
#define KC 64            // K elements (bytes, fp8) per smem chunk
#define NC (HH / KC)     // 16 chunks
#define NSTAGE 4
#define NTHREADS 128     // 4 warps, 64x64 warp tiles

#define WSCALE 64.0f
#define INV_WSCALE (1.0f / 64.0f)

// smem: rowIdx (512B pad to 1K) then 4 stages of (A 8K | B 8K)
#define STAGE_BYTES (2 * 128 * 64)
#define SM_STAGE0 1024
#define SMEM_TOTAL (SM_STAGE0 + NSTAGE * STAGE_BYTES)

// ---------------- scratch ----------------
__device__ int g_cnt[8];
__device__ int g_pos[BB];
__device__ int g_rows[6 * BB];
__device__ uint8_t g_a8[(size_t)5 * BB * HH];            // e4m3 gathered hidden
__device__ uint8_t g_w8[(size_t)NHEAD * LL * HH];        // e4m3 W * 64

// ---------------- PTX helpers ----------------
__device__ __forceinline__ uint32_t smem_u32(const void* p) {
    uint32_t a;
    asm("{ .reg .u64 t; cvta.to.shared.u64 t, %1; cvt.u32.u64 %0, t; }" : "=r"(a) : "l"(p));
    return a;
}
#define CP_ASYNC16(dst, src) \
    asm volatile("cp.async.cg.shared.global [%0], [%1], 16;" :: "r"(dst), "l"(src))
#define CP_COMMIT() asm volatile("cp.async.commit_group;" ::: "memory")
#define CP_WAIT2()  asm volatile("cp.async.wait_group 2;" ::: "memory")

// A fragment for m16n8k32 e4m3: 16 rows x 32 bytes of k.
// ldmatrix.x4.b16 over 16-byte "rows": lanes 0-15 -> rows 0-15 seg c16,
// lanes 16-31 -> rows 0-15 seg c16+1. Frag regs land as
// {rows g, k0-15}{g+8, k0-15}{g, k16-31}{g+8, k16-31} = fp8 mma A layout.
__device__ __forceinline__ void ld_frag4a(uint32_t* f, uint32_t sbase, int rowbase,
                                          int c16, int lane) {
    int r = rowbase + (lane & 15);
    int cc = c16 + (lane >> 4);
    uint32_t addr = sbase + r * 64 + (((cc ^ ((r >> 1) & 3))) << 4);
    asm volatile("ldmatrix.sync.aligned.m8n8.x4.shared.b16 {%0,%1,%2,%3}, [%4];"
                 : "=r"(f[0]), "=r"(f[1]), "=r"(f[2]), "=r"(f[3]) : "r"(addr));
}

// B fragments for two n8 tiles (16 n rows) at once:
// lanes 0-7: n0-7 seg c16; lanes 8-15: n0-7 seg c16+1;
// lanes 16-23: n8-15 seg c16; lanes 24-31: n8-15 seg c16+1.
// Frags: {tile0 reg0}{tile0 reg1}{tile1 reg0}{tile1 reg1}.
__device__ __forceinline__ void ld_frag4b(uint32_t* f, uint32_t sbase, int rowbase,
                                          int c16, int lane) {
    int r = rowbase + (lane & 7) + ((lane >> 4) << 3);
    int cc = c16 + ((lane >> 3) & 1);
    uint32_t addr = sbase + r * 64 + (((cc ^ ((r >> 1) & 3))) << 4);
    asm volatile("ldmatrix.sync.aligned.m8n8.x4.shared.b16 {%0,%1,%2,%3}, [%4];"
                 : "=r"(f[0]), "=r"(f[1]), "=r"(f[2]), "=r"(f[3]) : "r"(addr));
}

__device__ __forceinline__ void mma16832(float* d, const uint32_t* a,
                                         uint32_t b0, uint32_t b1) {
    asm volatile(
        "mma.sync.aligned.m16n8k32.row.col.f32.e4m3.e4m3.f32 "
        "{%0,%1,%2,%3}, {%4,%5,%6,%7}, {%8,%9}, {%0,%1,%2,%3};"
        : "+f"(d[0]), "+f"(d[1]), "+f"(d[2]), "+f"(d[3])
        : "r"(a[0]), "r"(a[1]), "r"(a[2]), "r"(a[3]), "r"(b0), "r"(b1));
}

__device__ __forceinline__ uint8_t to_e4m3(float x) {
    return (uint8_t)__nv_cvt_float_to_fp8(x, __NV_SATFINITE, __NV_E4M3);
}
__device__ __forceinline__ uint32_t pack4_e4m3(float4 f) {
    return (uint32_t)to_e4m3(f.x) | ((uint32_t)to_e4m3(f.y) << 8) |
           ((uint32_t)to_e4m3(f.z) << 16) | ((uint32_t)to_e4m3(f.w) << 24);
}

// ---------------- aux kernels ----------------
__global__ void init_kernel() {
    if (threadIdx.x < 8) g_cnt[threadIdx.x] = 0;
}

__global__ void bucket_kernel(const int* __restrict__ group) {
    int b = blockIdx.x * blockDim.x + threadIdx.x;
    if (b < BB) {
        int g = group[b];
        if (g < 0) g = 0;
        if (g > 5) g = 5;
        int pos = atomicAdd(&g_cnt[g], 1);
        g_pos[b] = pos;
        g_rows[g * BB + pos] = b;
    }
}

// W fp32 -> e4m3 * WSCALE; each thread handles 16 floats -> 16 bytes
__global__ void convert_w_kernel(const float* __restrict__ W) {
    int i = blockIdx.x * blockDim.x + threadIdx.x;
    const float4* src = reinterpret_cast<const float4*>(W) + (size_t)i * 4;
    uint4 o;
    float4 f0 = src[0], f1 = src[1], f2 = src[2], f3 = src[3];
    f0.x *= WSCALE; f0.y *= WSCALE; f0.z *= WSCALE; f0.w *= WSCALE;
    f1.x *= WSCALE; f1.y *= WSCALE; f1.z *= WSCALE; f1.w *= WSCALE;
    f2.x *= WSCALE; f2.y *= WSCALE; f2.z *= WSCALE; f2.w *= WSCALE;
    f3.x *= WSCALE; f3.y *= WSCALE; f3.z *= WSCALE; f3.w *= WSCALE;
    o.x = pack4_e4m3(f0); o.y = pack4_e4m3(f1);
    o.z = pack4_e4m3(f2); o.w = pack4_e4m3(f3);
    reinterpret_cast<uint4*>(g_w8)[i] = o;
}

// gather hidden rows into head-contiguous e4m3 buffer; 1 warp per row
__global__ void gather_a_kernel(const float* __restrict__ hs,
                                const int* __restrict__ group) {
    int b = (blockIdx.x * blockDim.x + threadIdx.x) >> 5;
    int lane = threadIdx.x & 31;
    if (b >= BB) return;
    int g = group[b];
    if (g < 0) g = 0;
    if (g > 5) g = 5;
    if (g == 5) return;
    size_t dst = (size_t)(g * BB + g_pos[b]) * HH;
    const float4* src = reinterpret_cast<const float4*>(hs + (size_t)b * HH);
    uint32_t* dp = reinterpret_cast<uint32_t*>(g_a8 + dst);
#pragma unroll
    for (int i = 0; i < 8; i++) {
        float4 f = src[lane + i * 32];
        dp[lane + i * 32] = pack4_e4m3(f);
    }
}

__global__ void fill_kernel(const int* __restrict__ labels, float* __restrict__ out) {
    for (int i = blockIdx.x; i < g_cnt[5]; i += gridDim.x) {
        int row = g_rows[5 * BB + i];
        float v = (float)labels[row];
        float4 v4 = make_float4(v, v, v, v);
        reinterpret_cast<float4*>(out + (size_t)row * LL)[threadIdx.x] = v4;
    }
}

// ---------------- FP8 MMA GEMM ----------------
// grid: (LL/TN=8, BB/TM=64, NHEAD). Early exit if row0 >= bucket count.
__global__ __launch_bounds__(NTHREADS)
void gemm_fp8_kernel(const float* __restrict__ bias, float* __restrict__ out) {
    const int head = blockIdx.z;
    const int cnt = g_cnt[head];
    const int row0 = blockIdx.y * TM;
    if (row0 >= cnt) return;
    const int col0 = blockIdx.x * TN;

    extern __shared__ char smem[];
    const uint32_t sb = smem_u32(smem);
    int* rowIdx_s = reinterpret_cast<int*>(smem);

    const int tid = threadIdx.x;
    const int wid = tid >> 5;
    const int lid = tid & 31;
    const int WM = (wid & 1) * 64;       // 2 warp-rows of 64
    const int WN = (wid >> 1) * 64;      // 2 warp-cols of 64

    if (tid < TM) {
        int r = row0 + tid;
        rowIdx_s[tid] = (r < cnt) ? g_rows[head * BB + r] : -1;
    }

    const uint8_t* __restrict__ amat = g_a8 + (size_t)(head * BB + row0) * HH;
    const uint8_t* __restrict__ bmat = g_w8 + ((size_t)head * LL + col0) * HH;

    // stage fill: 8 x 16B cp.async per thread (A,B: 128 rows x 64B each)
    auto fill_stage = [&](int s, int chunk) {
        const int k0 = chunk * KC;
        const uint32_t sbase = sb + SM_STAGE0 + s * STAGE_BYTES;
#pragma unroll
        for (int l = 0; l < 8; l++) {
            const int idx = l * NTHREADS + tid;        // 0..1023
            const int mat = idx >> 9;                  // 0=A 1=B
            const int q = idx & 511;
            const int r = q >> 2;
            const int seg = q & 3;
            const uint8_t* src = (mat ? bmat : amat) + (size_t)r * HH + k0 + seg * 16;
            uint32_t dst = sbase + mat * 8192 + r * 64 + ((seg ^ ((r >> 1) & 3)) << 4);
            CP_ASYNC16(dst, src);
        }
    };

    // prologue: chunks 0..2
    fill_stage(0, 0); CP_COMMIT();
    fill_stage(1, 1); CP_COMMIT();
    fill_stage(2, 2); CP_COMMIT();

    float acc[4][8][4];
#pragma unroll
    for (int i = 0; i < 4; i++)
#pragma unroll
        for (int j = 0; j < 8; j++)
#pragma unroll
            for (int k = 0; k < 4; k++) acc[i][j][k] = 0.0f;

    for (int c = 0; c < NC; c++) {
        CP_WAIT2();                 // chunk c resident
        __syncthreads();            // + readers of reused stage drained

        const uint32_t sbase = sb + SM_STAGE0 + (c % NSTAGE) * STAGE_BYTES;
        const uint32_t sA = sbase;
        const uint32_t sB = sbase + 8192;

#pragma unroll
        for (int kt = 0; kt < 2; kt++) {     // two k32 halves of the 64B chunk
            const int c16 = kt * 2;
            uint32_t bfr[16];
#pragma unroll
            for (int nb = 0; nb < 4; nb++) ld_frag4b(bfr + nb * 4, sB, WN + nb * 16, c16, lid);
            uint32_t afr[16];
#pragma unroll
            for (int mt = 0; mt < 4; mt++) ld_frag4a(afr + mt * 4, sA, WM + mt * 16, c16, lid);
#pragma unroll
            for (int mt = 0; mt < 4; mt++)
#pragma unroll
                for (int nb = 0; nb < 4; nb++) {
                    mma16832(acc[mt][nb * 2 + 0], afr + mt * 4, bfr[nb * 4 + 0], bfr[nb * 4 + 1]);
                    mma16832(acc[mt][nb * 2 + 1], afr + mt * 4, bfr[nb * 4 + 2], bfr[nb * 4 + 3]);
                }
        }

        if (c + 3 < NC) fill_stage((c + 3) % NSTAGE, c + 3);
        CP_COMMIT();                // keep group count uniform
    }

    // ---------------- epilogue ----------------
    const int groupID = lid >> 2;
    const int tig = lid & 3;
    const float* brow = bias + head * LL;

#pragma unroll
    for (int mt = 0; mt < 4; mt++) {
        const int mlo = WM + mt * 16 + groupID;
        const int r1 = rowIdx_s[mlo];
        const int r2 = rowIdx_s[mlo + 8];
#pragma unroll
        for (int nt = 0; nt < 8; nt++) {
            const int gc = col0 + WN + nt * 8 + tig * 2;
            const float2 bs = *reinterpret_cast<const float2*>(brow + gc);
            if (r1 >= 0) {
                float2 v = make_float2(acc[mt][nt][0] * INV_WSCALE + bs.x,
                                       acc[mt][nt][1] * INV_WSCALE + bs.y);
                *reinterpret_cast<float2*>(out + (size_t)r1 * LL + gc) = v;
            }
            if (r2 >= 0) {
                float2 v = make_float2(acc[mt][nt][2] * INV_WSCALE + bs.x,
                                       acc[mt][nt][3] * INV_WSCALE + bs.y);
                *reinterpret_cast<float2*>(out + (size_t)r2 * LL + gc) = v;
            }
        }
    }
}

// ---------------- launch ----------------
extern "C" void kernel_launch(void* const* d_in, const int* in_sizes, int n_in,
                              void* d_out, int out_size) {
    const float* hs     = (const float*)d_in[0];  // [B, H]
    const float* W      = (const float*)d_in[1];  // [5, L, H]
    const float* bias   = (const float*)d_in[2];  // [5, L]
    const int*   group  = (const int*)d_in[3];    // [B]
    const int*   labels = (const int*)d_in[4];    // [B]
    float* out = (float*)d_out;                   // [B, L]

    cudaFuncSetAttribute(gemm_fp8_kernel,
                         cudaFuncAttributeMaxDynamicSharedMemorySize, SMEM_TOTAL);

    init_kernel<<<1, 32>>>();
    bucket_kernel<<<BB / 256, 256>>>(group);
    convert_w_kernel<<<((size_t)NHEAD * LL * HH / 16) / 256, 256>>>(W);
    gather_a_kernel<<<BB * 32 / 256, 256>>>(hs, group);

    dim3 grid(LL / TN, BB / TM, NHEAD);
    gemm_fp8_kernel<<<grid, NTHREADS, SMEM_TOTAL>>>(bias, out);

    fill_kernel<<<2048, 256>>>(labels, out);
}

// round 8
// speedup vs baseline: 5.6759x; 1.0563x over previous
#include <cuda_runtime.h>
#include <cuda_fp16.h>
#include <cuda_fp8.h>
#include <stdint.h>

// ---------------- problem constants ----------------
#define BB 8192
#define HH 1024
#define LL 1024
#define NHEAD 5

// ---------------- GEMM config ----------------
#define TM 128
#define TN 128
#define KC 64            // K elements (bytes, fp8) per smem chunk
#define NC (HH / KC)     // 16 chunks
#define NSTAGE 4
#define NTHREADS 128     // 4 warps, 64x64 warp tiles

#define WSCALE 64.0f
#define INV_WSCALE (1.0f / 64.0f)

// smem: rowIdx (512B pad to 1K) then 4 stages of (A 8K | B 8K)
#define STAGE_BYTES (2 * 128 * 64)
#define SM_STAGE0 1024
#define SMEM_TOTAL (SM_STAGE0 + NSTAGE * STAGE_BYTES)

// prep kernel block ranges
#define PREP_A_BLOCKS 1024                   // 8 warps/block -> 8192 rows
#define PREP_W_BLOCKS 1280                   // 5M elems / 16 / 256
#define PREP_B_BLOCKS 32                     // 8192 / 256
#define PREP_BLOCKS (PREP_A_BLOCKS + PREP_W_BLOCKS + PREP_B_BLOCKS)

// ---------------- scratch ----------------
__device__ int g_cnt[8];
__device__ int g_rows[6 * BB];
__device__ uint8_t g_a8[(size_t)BB * HH];                // e4m3 hidden (natural order)
__device__ uint8_t g_w8[(size_t)NHEAD * LL * HH];        // e4m3 W * 64

// ---------------- PTX helpers ----------------
__device__ __forceinline__ uint32_t smem_u32(const void* p) {
    uint32_t a;
    asm("{ .reg .u64 t; cvta.to.shared.u64 t, %1; cvt.u32.u64 %0, t; }" : "=r"(a) : "l"(p));
    return a;
}
#define CP_ASYNC16(dst, src) \
    asm volatile("cp.async.cg.shared.global [%0], [%1], 16;" :: "r"(dst), "l"(src))
#define CP_COMMIT() asm volatile("cp.async.commit_group;" ::: "memory")
#define CP_WAIT2()  asm volatile("cp.async.wait_group 2;" ::: "memory")

// A fragment for m16n8k32 e4m3 (see R7 notes): lanes 0-15 rows, lanes 16-31 next 16B seg.
__device__ __forceinline__ void ld_frag4a(uint32_t* f, uint32_t sbase, int rowbase,
                                          int c16, int lane) {
    int r = rowbase + (lane & 15);
    int cc = c16 + (lane >> 4);
    uint32_t addr = sbase + r * 64 + (((cc ^ ((r >> 1) & 3))) << 4);
    asm volatile("ldmatrix.sync.aligned.m8n8.x4.shared.b16 {%0,%1,%2,%3}, [%4];"
                 : "=r"(f[0]), "=r"(f[1]), "=r"(f[2]), "=r"(f[3]) : "r"(addr));
}

// B fragments for two n8 tiles at once (layout per R7 notes).
__device__ __forceinline__ void ld_frag4b(uint32_t* f, uint32_t sbase, int rowbase,
                                          int c16, int lane) {
    int r = rowbase + (lane & 7) + ((lane >> 4) << 3);
    int cc = c16 + ((lane >> 3) & 1);
    uint32_t addr = sbase + r * 64 + (((cc ^ ((r >> 1) & 3))) << 4);
    asm volatile("ldmatrix.sync.aligned.m8n8.x4.shared.b16 {%0,%1,%2,%3}, [%4];"
                 : "=r"(f[0]), "=r"(f[1]), "=r"(f[2]), "=r"(f[3]) : "r"(addr));
}

__device__ __forceinline__ void mma16832(float* d, const uint32_t* a,
                                         uint32_t b0, uint32_t b1) {
    asm volatile(
        "mma.sync.aligned.m16n8k32.row.col.f32.e4m3.e4m3.f32 "
        "{%0,%1,%2,%3}, {%4,%5,%6,%7}, {%8,%9}, {%0,%1,%2,%3};"
        : "+f"(d[0]), "+f"(d[1]), "+f"(d[2]), "+f"(d[3])
        : "r"(a[0]), "r"(a[1]), "r"(a[2]), "r"(a[3]), "r"(b0), "r"(b1));
}

__device__ __forceinline__ uint8_t to_e4m3(float x) {
    return (uint8_t)__nv_cvt_float_to_fp8(x, __NV_SATFINITE, __NV_E4M3);
}
__device__ __forceinline__ uint32_t pack4_e4m3(float4 f) {
    return (uint32_t)to_e4m3(f.x) | ((uint32_t)to_e4m3(f.y) << 8) |
           ((uint32_t)to_e4m3(f.z) << 16) | ((uint32_t)to_e4m3(f.w) << 24);
}

// ---------------- aux kernels ----------------
__global__ void init_kernel() {
    if (threadIdx.x < 8) g_cnt[threadIdx.x] = 0;
}

// fused prep: [0, PREP_A_BLOCKS)            convert A rows + fill group-5 rows
//             [.., +PREP_W_BLOCKS)          convert W
//             [.., +PREP_B_BLOCKS)          bucket rows by head
__global__ __launch_bounds__(256)
void prep_kernel(const float* __restrict__ hs, const float* __restrict__ W,
                 const int* __restrict__ group, const int* __restrict__ labels,
                 float* __restrict__ out) {
    const int bx = blockIdx.x;
    if (bx < PREP_A_BLOCKS) {
        // warp per row
        const int row = bx * 8 + (threadIdx.x >> 5);
        const int lane = threadIdx.x & 31;
        int g = group[row];
        if (g < 0) g = 0;
        if (g > 5) g = 5;
        if (g == 5) {
            float v = (float)labels[row];
            float4 v4 = make_float4(v, v, v, v);
            float4* dp = reinterpret_cast<float4*>(out + (size_t)row * LL);
#pragma unroll
            for (int i = 0; i < 8; i++) dp[lane + i * 32] = v4;
        } else {
            const float4* src = reinterpret_cast<const float4*>(hs + (size_t)row * HH);
            uint32_t* dp = reinterpret_cast<uint32_t*>(g_a8 + (size_t)row * HH);
#pragma unroll
            for (int i = 0; i < 8; i++) dp[lane + i * 32] = pack4_e4m3(src[lane + i * 32]);
        }
    } else if (bx < PREP_A_BLOCKS + PREP_W_BLOCKS) {
        const int i = (bx - PREP_A_BLOCKS) * 256 + threadIdx.x;   // 16-float group
        const float4* src = reinterpret_cast<const float4*>(W) + (size_t)i * 4;
        float4 f0 = src[0], f1 = src[1], f2 = src[2], f3 = src[3];
        f0.x *= WSCALE; f0.y *= WSCALE; f0.z *= WSCALE; f0.w *= WSCALE;
        f1.x *= WSCALE; f1.y *= WSCALE; f1.z *= WSCALE; f1.w *= WSCALE;
        f2.x *= WSCALE; f2.y *= WSCALE; f2.z *= WSCALE; f2.w *= WSCALE;
        f3.x *= WSCALE; f3.y *= WSCALE; f3.z *= WSCALE; f3.w *= WSCALE;
        uint4 o;
        o.x = pack4_e4m3(f0); o.y = pack4_e4m3(f1);
        o.z = pack4_e4m3(f2); o.w = pack4_e4m3(f3);
        reinterpret_cast<uint4*>(g_w8)[i] = o;
    } else {
        const int b = (bx - PREP_A_BLOCKS - PREP_W_BLOCKS) * 256 + threadIdx.x;
        int g = group[b];
        if (g < 0) g = 0;
        if (g > 5) g = 5;
        int pos = atomicAdd(&g_cnt[g], 1);
        g_rows[g * BB + pos] = b;
    }
}

// ---------------- FP8 MMA GEMM ----------------
// grid: (LL/TN=8, BB/TM=64, NHEAD). Early exit if row0 >= bucket count.
__global__ __launch_bounds__(NTHREADS)
void gemm_fp8_kernel(const float* __restrict__ bias, float* __restrict__ out) {
    const int head = blockIdx.z;
    const int cnt = g_cnt[head];
    const int row0 = blockIdx.y * TM;
    if (row0 >= cnt) return;
    const int col0 = blockIdx.x * TN;

    extern __shared__ char smem[];
    const uint32_t sb = smem_u32(smem);
    int* rowIdx_s = reinterpret_cast<int*>(smem);

    const int tid = threadIdx.x;
    const int wid = tid >> 5;
    const int lid = tid & 31;
    const int WM = (wid & 1) * 64;       // 2 warp-rows of 64
    const int WN = (wid >> 1) * 64;      // 2 warp-cols of 64

    if (tid < TM) {
        int r = row0 + tid;
        rowIdx_s[tid] = (r < cnt) ? g_rows[head * BB + r] : -1;
    }
    __syncthreads();

    // per-thread fixed A rows for the indexed cp.async loads
    int arows[4];
#pragma unroll
    for (int l = 0; l < 4; l++) {
        int r = (l * NTHREADS + tid) >> 2;
        int v = rowIdx_s[r];
        arows[l] = (v < 0) ? 0 : v;      // clamp dead rows to row 0 (masked at epilogue)
    }

    const uint8_t* __restrict__ bmat = g_w8 + ((size_t)head * LL + col0) * HH;

    // stage fill: A indexed-gather + B dense, 8 x 16B cp.async per thread
    auto fill_stage = [&](int s, int chunk) {
        const int k0 = chunk * KC;
        const uint32_t sbase = sb + SM_STAGE0 + s * STAGE_BYTES;
#pragma unroll
        for (int l = 0; l < 4; l++) {    // A
            const int q = l * NTHREADS + tid;          // 0..511
            const int r = q >> 2;
            const int seg = q & 3;
            const uint8_t* src = g_a8 + (size_t)arows[l] * HH + k0 + seg * 16;
            uint32_t dst = sbase + r * 64 + ((seg ^ ((r >> 1) & 3)) << 4);
            CP_ASYNC16(dst, src);
        }
#pragma unroll
        for (int l = 0; l < 4; l++) {    // B
            const int q = l * NTHREADS + tid;
            const int r = q >> 2;
            const int seg = q & 3;
            const uint8_t* src = bmat + (size_t)r * HH + k0 + seg * 16;
            uint32_t dst = sbase + 8192 + r * 64 + ((seg ^ ((r >> 1) & 3)) << 4);
            CP_ASYNC16(dst, src);
        }
    };

    // prologue: chunks 0..2
    fill_stage(0, 0); CP_COMMIT();
    fill_stage(1, 1); CP_COMMIT();
    fill_stage(2, 2); CP_COMMIT();

    float acc[4][8][4];
#pragma unroll
    for (int i = 0; i < 4; i++)
#pragma unroll
        for (int j = 0; j < 8; j++)
#pragma unroll
            for (int k = 0; k < 4; k++) acc[i][j][k] = 0.0f;

    for (int c = 0; c < NC; c++) {
        CP_WAIT2();                 // chunk c resident
        __syncthreads();            // + readers of reused stage drained

        // prefetch FIRST so LSU runs under the tensor pipe
        if (c + 3 < NC) fill_stage((c + 3) % NSTAGE, c + 3);
        CP_COMMIT();                // keep group count uniform

        const uint32_t sbase = sb + SM_STAGE0 + (c % NSTAGE) * STAGE_BYTES;
        const uint32_t sA = sbase;
        const uint32_t sB = sbase + 8192;

#pragma unroll
        for (int kt = 0; kt < 2; kt++) {     // two k32 halves of the 64B chunk
            const int c16 = kt * 2;
            uint32_t bfr[16];
#pragma unroll
            for (int nb = 0; nb < 4; nb++) ld_frag4b(bfr + nb * 4, sB, WN + nb * 16, c16, lid);
            uint32_t afr[16];
#pragma unroll
            for (int mt = 0; mt < 4; mt++) ld_frag4a(afr + mt * 4, sA, WM + mt * 16, c16, lid);
#pragma unroll
            for (int mt = 0; mt < 4; mt++)
#pragma unroll
                for (int nb = 0; nb < 4; nb++) {
                    mma16832(acc[mt][nb * 2 + 0], afr + mt * 4, bfr[nb * 4 + 0], bfr[nb * 4 + 1]);
                    mma16832(acc[mt][nb * 2 + 1], afr + mt * 4, bfr[nb * 4 + 2], bfr[nb * 4 + 3]);
                }
        }
    }

    // ---------------- epilogue ----------------
    const int groupID = lid >> 2;
    const int tig = lid & 3;
    const float* brow = bias + head * LL;

#pragma unroll
    for (int mt = 0; mt < 4; mt++) {
        const int mlo = WM + mt * 16 + groupID;
        const int r1 = rowIdx_s[mlo];
        const int r2 = rowIdx_s[mlo + 8];
#pragma unroll
        for (int nt = 0; nt < 8; nt++) {
            const int gc = col0 + WN + nt * 8 + tig * 2;
            const float2 bs = *reinterpret_cast<const float2*>(brow + gc);
            if (r1 >= 0) {
                float2 v = make_float2(acc[mt][nt][0] * INV_WSCALE + bs.x,
                                       acc[mt][nt][1] * INV_WSCALE + bs.y);
                *reinterpret_cast<float2*>(out + (size_t)r1 * LL + gc) = v;
            }
            if (r2 >= 0) {
                float2 v = make_float2(acc[mt][nt][2] * INV_WSCALE + bs.x,
                                       acc[mt][nt][3] * INV_WSCALE + bs.y);
                *reinterpret_cast<float2*>(out + (size_t)r2 * LL + gc) = v;
            }
        }
    }
}

// ---------------- launch ----------------
extern "C" void kernel_launch(void* const* d_in, const int* in_sizes, int n_in,
                              void* d_out, int out_size) {
    const float* hs     = (const float*)d_in[0];  // [B, H]
    const float* W      = (const float*)d_in[1];  // [5, L, H]
    const float* bias   = (const float*)d_in[2];  // [5, L]
    const int*   group  = (const int*)d_in[3];    // [B]
    const int*   labels = (const int*)d_in[4];    // [B]
    float* out = (float*)d_out;                   // [B, L]

    cudaFuncSetAttribute(gemm_fp8_kernel,
                         cudaFuncAttributeMaxDynamicSharedMemorySize, SMEM_TOTAL);

    init_kernel<<<1, 32>>>();
    prep_kernel<<<PREP_BLOCKS, 256>>>(hs, W, group, labels, out);

    dim3 grid(LL / TN, BB / TM, NHEAD);
    gemm_fp8_kernel<<<grid, NTHREADS, SMEM_TOTAL>>>(bias, out);
}